// round 9
// baseline (speedup 1.0000x reference)
#include <cuda_runtime.h>
#include <cuda_bf16.h>
#include <cstdint>

// ---------------------------------------------------------------------------
// Dcls1d via mma.sync (HMMA) bf16 split-GEMM with ACTIVE-d COMPACTION.
//   out[b,o,t] = bias[o] + sum_{d,i} K2[d,o,i] * x[b,i,t+d-16]
//   Most K2 d-slices are exactly zero (P ~ clip(0.5*N)); per-o nonzero masks
//   stored per build-block (plain stores, no atomics/reset), OR-reduced in
//   conv prologue. fp32 = bf16 hi+lo, 3 products (hh,hl,lh), fp32 accum.
// R9: block 128o x 128t, 256 thr (8 warps, warp 32o x 64t), 2 blocks/SM.
//     Fused prep kernel. 2 launches total.
// ---------------------------------------------------------------------------

#define B_   8
#define C_   256
#define T_   2048
#define O_   256
#define DKS_ 33
#define KC_  16
#define TP_  2080   // 16 + 2048 + 16 padded time rows

__device__ __nv_bfloat16 g_Khi[DKS_ * O_ * C_];   // [d][o][i]
__device__ __nv_bfloat16 g_Klo[DKS_ * O_ * C_];
__device__ __nv_bfloat16 g_Xhi[B_ * TP_ * C_];    // [b][t+16][i]
__device__ __nv_bfloat16 g_Xlo[B_ * TP_ * C_];
__device__ unsigned long long g_maskblk[O_];      // per-o nonzero-slice mask

// ---- PTX helpers -----------------------------------------------------------
__device__ __forceinline__ uint32_t smem_u32(const void* p) {
    uint32_t a;
    asm("{ .reg .u64 t; cvta.to.shared.u64 t, %1; cvt.u32.u64 %0, t; }"
        : "=r"(a) : "l"(p));
    return a;
}
__device__ __forceinline__ void cpa16(uint32_t dst, const void* src) {
    asm volatile("cp.async.ca.shared.global [%0], [%1], 16;" :: "r"(dst), "l"(src));
}
#define CP_COMMIT() asm volatile("cp.async.commit_group;" ::: "memory")
#define CP_WAIT0()  asm volatile("cp.async.wait_group 0;" ::: "memory")

__device__ __forceinline__ void ldmx4(uint32_t* r, uint32_t addr) {
    asm volatile("ldmatrix.sync.aligned.m8n8.x4.shared.b16 {%0,%1,%2,%3}, [%4];"
                 : "=r"(r[0]), "=r"(r[1]), "=r"(r[2]), "=r"(r[3]) : "r"(addr));
}
#define MMA(dv, a, b0v, b1v)                                                   \
    asm volatile("mma.sync.aligned.m16n8k16.row.col.f32.bf16.bf16.f32 "        \
                 "{%0,%1,%2,%3},{%4,%5,%6,%7},{%8,%9},{%0,%1,%2,%3};"          \
                 : "+f"((dv)[0]), "+f"((dv)[1]), "+f"((dv)[2]), "+f"((dv)[3])  \
                 : "r"((a)[0]), "r"((a)[1]), "r"((a)[2]), "r"((a)[3]),         \
                   "r"(b0v), "r"(b1v))

// ---------------------------------------------------------------------------
// Fused prep kernel: blocks [0,4096) do x transpose/split; [4096,4352) build K2.
// ---------------------------------------------------------------------------
__global__ void prep(const float* __restrict__ x,
                     const float* __restrict__ w,
                     const float* __restrict__ P) {
    __shared__ float sm[32][33];
    __shared__ unsigned long long s_m[8];
    const int tid = threadIdx.x;

    if (blockIdx.x < 4096) {
        // ---- xsplit: grid decode (64 t-tiles, 8 i-tiles, 8 batches) ----
        int blk = blockIdx.x;
        int t0 = (blk & 63) * 32;
        int i0 = ((blk >> 6) & 7) * 32;
        int b  = blk >> 9;
        int tl = tid & 31, th = tid >> 5;

        // zero pads (first/last 16 rows of this batch, this i-stripe)
        if ((blk & 63) == 0) {
#pragma unroll
            for (int k = 0; k < 2; ++k) {
                int e = tid + k * 256;            // 512 = 16 rows x 32 cols
                int r = e >> 5, cc = e & 31;
                size_t o1 = ((size_t)b * TP_ + r) * C_ + i0 + cc;
                size_t o2 = ((size_t)b * TP_ + (TP_ - 16 + r)) * C_ + i0 + cc;
                g_Xhi[o1] = __float2bfloat16(0.f);
                g_Xlo[o1] = __float2bfloat16(0.f);
                g_Xhi[o2] = __float2bfloat16(0.f);
                g_Xlo[o2] = __float2bfloat16(0.f);
            }
        }
#pragma unroll
        for (int k = 0; k < 4; ++k) {
            int i = i0 + th + k * 8;
            sm[th + k * 8][tl] = x[((size_t)b * C_ + i) * T_ + t0 + tl];
        }
        __syncthreads();
#pragma unroll
        for (int k = 0; k < 4; ++k) {
            int t = t0 + th + k * 8;
            float v = sm[tl][th + k * 8];
            __nv_bfloat16 h = __float2bfloat16(v);
            __nv_bfloat16 l = __float2bfloat16(v - __bfloat162float(h));
            size_t idx = ((size_t)b * TP_ + t + 16) * C_ + i0 + tl;
            g_Xhi[idx] = h;
            g_Xlo[idx] = l;
        }
    } else {
        // ---- build_k2: block bk handles o = bk, all 256 i ----
        int bk = blockIdx.x - 4096;
        int oi = bk * 256 + tid;
        int ig = tid;
        float acc[DKS_];
#pragma unroll
        for (int d = 0; d < DKS_; ++d) acc[d] = 0.f;

        const float* Prow  = P + (size_t)oi * KC_;
        const float* P0row = P + (size_t)ig * KC_;    // out-channel 0 (frac src)
        const float* Wrow  = w + (size_t)oi * KC_;
#pragma unroll
        for (int k = 0; k < KC_; ++k) {
            float pp  = Prow[k] + 16.f;
            int   p   = (int)floorf(pp);
            float pp0 = P0row[k] + 16.f;
            float fr  = pp0 - floorf(pp0);
            float wv  = Wrow[k];
            if (p >= 0 && p < DKS_)         acc[p]     += wv * (1.f - fr);
            if (p + 1 >= 0 && p + 1 < DKS_) acc[p + 1] += wv * fr;
        }
        unsigned long long bits = 0ull;
#pragma unroll
        for (int d = 0; d < DKS_; ++d) {
            float v = acc[d];
            if (v != 0.f) bits |= 1ull << d;
            __nv_bfloat16 h = __float2bfloat16(v);
            __nv_bfloat16 l = __float2bfloat16(v - __bfloat162float(h));
            size_t idx = (size_t)(d * O_ + bk) * C_ + ig;
            g_Khi[idx] = h;
            g_Klo[idx] = l;
        }
#pragma unroll
        for (int s = 16; s > 0; s >>= 1)
            bits |= __shfl_xor_sync(0xffffffffu, bits, s);
        if ((tid & 31) == 0) s_m[tid >> 5] = bits;
        __syncthreads();
        if (tid == 0) {
            unsigned long long m = 0ull;
#pragma unroll
            for (int q = 0; q < 8; ++q) m |= s_m[q];
            g_maskblk[bk] = m;    // plain store, rewritten every call
        }
    }
}

// ---------------------------------------------------------------------------
// GEMM kernel.
// Block: 128 o x 128 t, 256 threads (8 warps: 4 M x 2 N, warp = 32 o x 64 t).
// 2 blocks/SM. ic-chunk = 32 i (8 chunks). smem rows 80B (conflict-free LDSM).
//   A (K2[d] tile): 128 x 32 i, hi+lo, double buffered: 2 x 20480 B
//   X tile:         160 x 32 i, hi+lo:                   25600 B
// ---------------------------------------------------------------------------
#define ROWB   80u
#define A_TS   10240u      // one A tensor (128*80)
#define A_BUF  20480u      // hi+lo pair
#define X_OFF  40960u
#define X_TS   12800u      // one X tensor (160*80)
#define DSMEM  (40960u + 25600u + 128u)

__device__ __forceinline__ void stage_A(uint32_t A0, int d, int slot,
                                        int o0, int ic, int tid) {
    uint32_t Ab = A0 + (uint32_t)slot * A_BUF;
#pragma unroll
    for (int k = 0; k < 4; ++k) {
        int idx = tid + k * 256;                 // 1024 chunks
        int tn  = idx >> 9;
        int r   = (idx >> 2) & 127;
        int c   = idx & 3;
        const __nv_bfloat16* src = (tn ? g_Klo : g_Khi)
            + ((size_t)(d * 256 + o0 + r) * 256 + ic * 32 + c * 8);
        cpa16(Ab + (uint32_t)tn * A_TS + r * ROWB + c * 16, src);
    }
}

__global__ __launch_bounds__(256, 2)
void conv_mma(const float* __restrict__ bias, float* __restrict__ out) {
    extern __shared__ char dsm_raw[];
    uint32_t raw  = smem_u32(dsm_raw);
    uint32_t base = (raw + 127u) & ~127u;

    __shared__ unsigned long long s_part[4];
    __shared__ int s_act[DKS_];
    __shared__ int s_n;

    const int tid  = threadIdx.x;
    const int lane = tid & 31, w = tid >> 5;
    const int wm = w & 3, wn = w >> 2;            // 4 M-warps x 2 N-warps
    const int b  = blockIdx.x >> 4;
    const int t0 = (blockIdx.x & 15) * 128;
    const int tile = blockIdx.y;
    const int o0 = tile * 128;

    // ---- prologue: OR-reduce 128 per-o masks -> active-d list ----
    if (tid < 128) {
        unsigned long long m = g_maskblk[o0 + tid];
#pragma unroll
        for (int s = 16; s > 0; s >>= 1)
            m |= __shfl_xor_sync(0xffffffffu, m, s);
        if (lane == 0) s_part[w] = m;
    }
    __syncthreads();
    if (tid == 0) {
        unsigned long long m = s_part[0] | s_part[1] | s_part[2] | s_part[3];
        int n = 0;
        for (int d = 0; d < DKS_; ++d)
            if (m & (1ull << d)) s_act[n++] = d;
        s_n = n;
    }
    __syncthreads();
    const int n_act = s_n;

    const uint32_t A0 = base;
    const uint32_t X0 = base + X_OFF;

    float acc[2][8][4];                           // [mi][p*2+nn][quad]
#pragma unroll
    for (int mi = 0; mi < 2; ++mi)
#pragma unroll
        for (int nf = 0; nf < 8; ++nf)
#pragma unroll
            for (int q = 0; q < 4; ++q) acc[mi][nf][q] = 0.f;

    // ldmatrix per-lane row/col offsets
    const uint32_t a_r = (lane & 7) + 8 * ((lane >> 3) & 1);
    const uint32_t a_c = (uint32_t)(lane >> 4) * 16;
    const uint32_t b_r = (lane & 7) + 8 * (lane >> 4);
    const uint32_t b_c = (uint32_t)((lane >> 3) & 1) * 16;

    if (n_act > 0) {
        for (int ic = 0; ic < 8; ++ic) {
            __syncthreads();    // protect X & A buffers vs previous ic's compute
            // ---- stage X tile (160 rows x 32 i, hi+lo): 1280 x 16B chunks ----
#pragma unroll
            for (int k = 0; k < 5; ++k) {
                int idx = tid + k * 256;
                int tn  = idx >= 640;
                int r   = (idx - tn * 640) >> 2;
                int c   = idx & 3;
                const __nv_bfloat16* src = (tn ? g_Xlo : g_Xhi)
                    + ((size_t)(b * TP_ + t0 + r) * 256 + ic * 32 + c * 8);
                cpa16(X0 + (uint32_t)tn * X_TS + r * ROWB + c * 16, src);
            }
            // ---- stage A(act[0]) into buf0 ----
            stage_A(A0, s_act[0], 0, o0, ic, tid);
            CP_COMMIT();

#pragma unroll 1
            for (int j = 0; j < n_act; ++j) {
                const int d = s_act[j];
                CP_WAIT0();        // A(j) (and X on j=0) landed for this thread
                __syncthreads();   // visible to all; all done with buf (j+1)&1

                if (j < n_act - 1) {   // overlap A(j+1) copy with compute(j)
                    stage_A(A0, s_act[j + 1], (j + 1) & 1, o0, ic, tid);
                    CP_COMMIT();
                }

                const uint32_t Ab = A0 + (uint32_t)(j & 1) * A_BUF;
#pragma unroll
                for (int kk = 0; kk < 2; ++kk) {
                    uint32_t ah[2][4], al[2][4];
#pragma unroll
                    for (int mi = 0; mi < 2; ++mi) {
                        uint32_t ad = Ab + (wm * 32 + mi * 16 + a_r) * ROWB
                                    + kk * 32 + a_c;
                        ldmx4(ah[mi], ad);
                        ldmx4(al[mi], ad + A_TS);
                    }
#pragma unroll
                    for (int p = 0; p < 4; ++p) {
                        uint32_t bh[4], bl[4];
                        uint32_t bd = X0 + (wn * 64 + d + p * 16 + b_r) * ROWB
                                    + kk * 32 + b_c;
                        ldmx4(bh, bd);
                        ldmx4(bl, bd + X_TS);
#pragma unroll
                        for (int mi = 0; mi < 2; ++mi)
#pragma unroll
                            for (int nn = 0; nn < 2; ++nn) {
                                MMA(acc[mi][p * 2 + nn], ah[mi], bh[2 * nn], bh[2 * nn + 1]);
                                MMA(acc[mi][p * 2 + nn], ah[mi], bl[2 * nn], bl[2 * nn + 1]);
                                MMA(acc[mi][p * 2 + nn], al[mi], bh[2 * nn], bh[2 * nn + 1]);
                            }
                    }
                }
            }
        }
    }

    // ---- epilogue: add bias, store float2 ----
    const int g = lane >> 2, tg = lane & 3;
#pragma unroll
    for (int mi = 0; mi < 2; ++mi) {
        int o1 = o0 + wm * 32 + mi * 16 + g;
        float bv1 = bias[o1], bv2 = bias[o1 + 8];
        float* r1 = out + ((size_t)(b * O_ + o1)) * T_ + t0 + wn * 64 + tg * 2;
        float* r2 = r1 + 8 * T_;
#pragma unroll
        for (int nf = 0; nf < 8; ++nf) {
            float2 v1 = make_float2(acc[mi][nf][0] + bv1, acc[mi][nf][1] + bv1);
            float2 v2 = make_float2(acc[mi][nf][2] + bv2, acc[mi][nf][3] + bv2);
            *(float2*)(r1 + nf * 8) = v1;
            *(float2*)(r2 + nf * 8) = v2;
        }
    }
}

// ---------------------------------------------------------------------------
// Launch (2 kernels)
// ---------------------------------------------------------------------------
extern "C" void kernel_launch(void* const* d_in, const int* in_sizes, int n_in,
                              void* d_out, int out_size) {
    const float* x      = (const float*)d_in[0];
    const float* weight = (const float*)d_in[1];
    const float* P      = (const float*)d_in[2];
    const float* bias   = (const float*)d_in[3];
    float* out          = (float*)d_out;

    prep<<<4096 + 256, 256>>>(x, weight, P);

    cudaFuncSetAttribute(conv_mma, cudaFuncAttributeMaxDynamicSharedMemorySize, DSMEM);
    conv_mma<<<dim3(128, 2), 256, DSMEM>>>(bias, out);
}

// round 10
// speedup vs baseline: 1.0254x; 1.0254x over previous
#include <cuda_runtime.h>
#include <cuda_bf16.h>
#include <cstdint>

// ---------------------------------------------------------------------------
// Dcls1d via mma.sync (HMMA) bf16 split-GEMM with ACTIVE-d COMPACTION.
//   out[b,o,t] = bias[o] + sum_{d,i} K2[d,o,i] * x[b,i,t+d-16]
//   Most K2 d-slices are exactly zero (P ~ clip(0.5*N)); per-o nonzero masks
//   (plain stores, no atomics), OR-reduced in conv prologue.
//   fp32 = bf16 hi+lo, 3 products (hh,hl,lh), fp32 accum.
// R10: ALL active-d A tiles staged per ic-chunk (8 smem slots) ->
//      ONE wait + ONE syncthreads per ic; d-loop fully barrier-free.
// ---------------------------------------------------------------------------

#define B_   8
#define C_   256
#define T_   2048
#define O_   256
#define DKS_ 33
#define KC_  16
#define TP_  2080   // 16 + 2048 + 16 padded time rows

__device__ __nv_bfloat16 g_Khi[DKS_ * O_ * C_];   // [d][o][i]
__device__ __nv_bfloat16 g_Klo[DKS_ * O_ * C_];
__device__ __nv_bfloat16 g_Xhi[B_ * TP_ * C_];    // [b][t+16][i]
__device__ __nv_bfloat16 g_Xlo[B_ * TP_ * C_];
__device__ unsigned long long g_maskblk[O_];      // per-o nonzero-slice mask

// ---- PTX helpers -----------------------------------------------------------
__device__ __forceinline__ uint32_t smem_u32(const void* p) {
    uint32_t a;
    asm("{ .reg .u64 t; cvta.to.shared.u64 t, %1; cvt.u32.u64 %0, t; }"
        : "=r"(a) : "l"(p));
    return a;
}
__device__ __forceinline__ void cpa16(uint32_t dst, const void* src) {
    asm volatile("cp.async.ca.shared.global [%0], [%1], 16;" :: "r"(dst), "l"(src));
}
#define CP_COMMIT() asm volatile("cp.async.commit_group;" ::: "memory")
#define CP_WAIT0()  asm volatile("cp.async.wait_group 0;" ::: "memory")

__device__ __forceinline__ void ldmx4(uint32_t* r, uint32_t addr) {
    asm volatile("ldmatrix.sync.aligned.m8n8.x4.shared.b16 {%0,%1,%2,%3}, [%4];"
                 : "=r"(r[0]), "=r"(r[1]), "=r"(r[2]), "=r"(r[3]) : "r"(addr));
}
#define MMA(dv, a, b0v, b1v)                                                   \
    asm volatile("mma.sync.aligned.m16n8k16.row.col.f32.bf16.bf16.f32 "        \
                 "{%0,%1,%2,%3},{%4,%5,%6,%7},{%8,%9},{%0,%1,%2,%3};"          \
                 : "+f"((dv)[0]), "+f"((dv)[1]), "+f"((dv)[2]), "+f"((dv)[3])  \
                 : "r"((a)[0]), "r"((a)[1]), "r"((a)[2]), "r"((a)[3]),         \
                   "r"(b0v), "r"(b1v))

// ---------------------------------------------------------------------------
// Kernel A: transpose+split x -> g_Xhi/lo [b][t+16][i]; zero pads.
// ---------------------------------------------------------------------------
__global__ void xsplit(const float* __restrict__ x) {
    __shared__ float sm[32][33];
    int t0 = blockIdx.x * 32, i0 = blockIdx.y * 32, b = blockIdx.z;
    int tid = threadIdx.x;
    int tl = tid & 31, th = tid >> 5;

    // zero pads (first/last 16 rows of this batch, this i-stripe)
    if (blockIdx.x == 0) {
#pragma unroll
        for (int k = 0; k < 2; ++k) {
            int e = tid + k * 256;            // 512 = 16 rows x 32 cols
            int r = e >> 5, cc = e & 31;
            size_t o1 = ((size_t)b * TP_ + r) * C_ + i0 + cc;
            size_t o2 = ((size_t)b * TP_ + (TP_ - 16 + r)) * C_ + i0 + cc;
            g_Xhi[o1] = __float2bfloat16(0.f);
            g_Xlo[o1] = __float2bfloat16(0.f);
            g_Xhi[o2] = __float2bfloat16(0.f);
            g_Xlo[o2] = __float2bfloat16(0.f);
        }
    }
#pragma unroll
    for (int k = 0; k < 4; ++k) {
        int i = i0 + th + k * 8;
        sm[th + k * 8][tl] = x[((size_t)b * C_ + i) * T_ + t0 + tl];
    }
    __syncthreads();
#pragma unroll
    for (int k = 0; k < 4; ++k) {
        int t = t0 + th + k * 8;
        float v = sm[tl][th + k * 8];
        __nv_bfloat16 h = __float2bfloat16(v);
        __nv_bfloat16 l = __float2bfloat16(v - __bfloat162float(h));
        size_t idx = ((size_t)b * TP_ + t + 16) * C_ + i0 + tl;
        g_Xhi[idx] = h;
        g_Xlo[idx] = l;
    }
}

// ---------------------------------------------------------------------------
// Kernel B: build K2 (bf16 hi/lo) [d][o][i]; per-o mask via plain store.
// Block bk <-> out-channel bk; thread = input channel.
// ---------------------------------------------------------------------------
__global__ void build_k2(const float* __restrict__ w, const float* __restrict__ P) {
    __shared__ unsigned long long s_m[8];
    int bk = blockIdx.x;
    int tid = threadIdx.x;
    int oi = bk * 256 + tid;
    float acc[DKS_];
#pragma unroll
    for (int d = 0; d < DKS_; ++d) acc[d] = 0.f;

    const float* Prow  = P + (size_t)oi * KC_;
    const float* P0row = P + (size_t)tid * KC_;   // out-channel 0 (frac source)
    const float* Wrow  = w + (size_t)oi * KC_;
#pragma unroll
    for (int k = 0; k < KC_; ++k) {
        float pp  = Prow[k] + 16.f;
        int   p   = (int)floorf(pp);
        float pp0 = P0row[k] + 16.f;
        float fr  = pp0 - floorf(pp0);
        float wv  = Wrow[k];
        if (p >= 0 && p < DKS_)         acc[p]     += wv * (1.f - fr);
        if (p + 1 >= 0 && p + 1 < DKS_) acc[p + 1] += wv * fr;
    }
    unsigned long long bits = 0ull;
#pragma unroll
    for (int d = 0; d < DKS_; ++d) {
        float v = acc[d];
        if (v != 0.f) bits |= 1ull << d;
        __nv_bfloat16 h = __float2bfloat16(v);
        __nv_bfloat16 l = __float2bfloat16(v - __bfloat162float(h));
        size_t idx = (size_t)(d * O_ + bk) * C_ + tid;
        g_Khi[idx] = h;
        g_Klo[idx] = l;
    }
#pragma unroll
    for (int s = 16; s > 0; s >>= 1)
        bits |= __shfl_xor_sync(0xffffffffu, bits, s);
    if ((tid & 31) == 0) s_m[tid >> 5] = bits;
    __syncthreads();
    if (tid == 0) {
        unsigned long long m = 0ull;
#pragma unroll
        for (int q = 0; q < 8; ++q) m |= s_m[q];
        g_maskblk[bk] = m;       // plain store, rewritten every call
    }
}

// ---------------------------------------------------------------------------
// Kernel C: the GEMM.
// Block: 128 o x 256 t, 512 threads (16 warps: 4Mx4N, warp = 32 o x 64 t).
// ic-chunk = 32 i (8 chunks). smem rows 80B stride (conflict-free LDSM).
//   A: up to 8 d-slots, each 128 x 32 i hi+lo = 8 x 20480 B
//   X: 288 x 32 i, hi+lo = 2 x 23040 B
// One wait + one barrier per (ic, d-group); d-loop barrier-free.
// ---------------------------------------------------------------------------
#define ROWB   80u
#define A_TS   10240u      // one A tensor (128*80)
#define A_BUF  20480u      // hi+lo pair (one d-slot)
#define NA_MAX 8
#define X_OFF  (NA_MAX * A_BUF)           // 163840
#define X_TS   23040u      // one X tensor (288*80)
#define DSMEM  (X_OFF + 2u * X_TS + 128u) // 210048

__device__ __forceinline__ void stage_A(uint32_t A0, int d, int slot,
                                        int o0, int ic, int tid) {
    uint32_t Ab = A0 + (uint32_t)slot * A_BUF;
#pragma unroll
    for (int k = 0; k < 2; ++k) {
        int idx = tid + k * 512;                 // 1024 chunks (hi+lo)
        int tn  = idx >> 9;
        int r   = (idx >> 2) & 127;
        int c   = idx & 3;
        const __nv_bfloat16* src = (tn ? g_Klo : g_Khi)
            + ((size_t)(d * 256 + o0 + r) * 256 + ic * 32 + c * 8);
        cpa16(Ab + (uint32_t)tn * A_TS + r * ROWB + c * 16, src);
    }
}

__global__ __launch_bounds__(512, 1)
void conv_mma(const float* __restrict__ bias, float* __restrict__ out) {
    extern __shared__ char dsm_raw[];
    uint32_t raw  = smem_u32(dsm_raw);
    uint32_t base = (raw + 127u) & ~127u;

    __shared__ unsigned long long s_part[4];
    __shared__ int s_act[DKS_];
    __shared__ int s_n;

    const int tid  = threadIdx.x;
    const int lane = tid & 31, w = tid >> 5;
    const int wm = w & 3, wn = w >> 2;            // 4 M-warps x 4 N-warps
    const int b  = blockIdx.x >> 3;
    const int t0 = (blockIdx.x & 7) * 256;
    const int tile = blockIdx.y;
    const int o0 = tile * 128;

    // ---- prologue: OR-reduce 128 per-o masks -> active-d list ----
    if (tid < 128) {
        unsigned long long m = g_maskblk[o0 + tid];
#pragma unroll
        for (int s = 16; s > 0; s >>= 1)
            m |= __shfl_xor_sync(0xffffffffu, m, s);
        if (lane == 0) s_part[w] = m;
    }
    __syncthreads();
    if (tid == 0) {
        unsigned long long m = s_part[0] | s_part[1] | s_part[2] | s_part[3];
        int n = 0;
        for (int d = 0; d < DKS_; ++d)
            if (m & (1ull << d)) s_act[n++] = d;
        s_n = n;
    }
    __syncthreads();
    const int n_act = s_n;

    const uint32_t A0 = base;
    const uint32_t X0 = base + X_OFF;

    float acc[2][8][4];                           // [mi][p*2+nn][quad]
#pragma unroll
    for (int mi = 0; mi < 2; ++mi)
#pragma unroll
        for (int nf = 0; nf < 8; ++nf)
#pragma unroll
            for (int q = 0; q < 4; ++q) acc[mi][nf][q] = 0.f;

    // ldmatrix per-lane row/col offsets
    const uint32_t a_r = (lane & 7) + 8 * ((lane >> 3) & 1);
    const uint32_t a_c = (uint32_t)(lane >> 4) * 16;
    const uint32_t b_r = (lane & 7) + 8 * (lane >> 4);
    const uint32_t b_c = (uint32_t)((lane >> 3) & 1) * 16;

    for (int ic = 0; ic < 8 && n_act > 0; ++ic) {
        for (int g0 = 0; g0 < n_act; g0 += NA_MAX) {
            const int gn = (n_act - g0 < NA_MAX) ? (n_act - g0) : NA_MAX;

            __syncthreads();    // buffers free (prev group/ic fully computed)
            if (g0 == 0) {
                // ---- stage X tile (288 rows x 32 i, hi+lo): 2304 chunks ----
#pragma unroll
                for (int k = 0; k < 5; ++k) {
                    int idx = tid + k * 512;
                    if (idx < 2304) {
                        int tn  = idx >= 1152;
                        int r   = (idx - tn * 1152) >> 2;
                        int c   = idx & 3;
                        const __nv_bfloat16* src = (tn ? g_Xlo : g_Xhi)
                            + ((size_t)(b * TP_ + t0 + r) * 256 + ic * 32 + c * 8);
                        cpa16(X0 + (uint32_t)tn * X_TS + r * ROWB + c * 16, src);
                    }
                }
            }
            // ---- stage ALL A tiles of this d-group ----
            for (int j = 0; j < gn; ++j)
                stage_A(A0, s_act[g0 + j], j, o0, ic, tid);
            CP_COMMIT();
            CP_WAIT0();
            __syncthreads();

            // ---- compute: barrier-free d-loop ----
#pragma unroll 1
            for (int j = 0; j < gn; ++j) {
                const int d = s_act[g0 + j];
                const uint32_t Ab = A0 + (uint32_t)j * A_BUF;
#pragma unroll
                for (int kk = 0; kk < 2; ++kk) {
                    uint32_t ah[2][4], al[2][4];
#pragma unroll
                    for (int mi = 0; mi < 2; ++mi) {
                        uint32_t ad = Ab + (wm * 32 + mi * 16 + a_r) * ROWB
                                    + kk * 32 + a_c;
                        ldmx4(ah[mi], ad);
                        ldmx4(al[mi], ad + A_TS);
                    }
#pragma unroll
                    for (int p = 0; p < 4; ++p) {
                        uint32_t bh[4], bl[4];
                        uint32_t bd = X0 + (wn * 64 + d + p * 16 + b_r) * ROWB
                                    + kk * 32 + b_c;
                        ldmx4(bh, bd);
                        ldmx4(bl, bd + X_TS);
#pragma unroll
                        for (int mi = 0; mi < 2; ++mi)
#pragma unroll
                            for (int nn = 0; nn < 2; ++nn) {
                                MMA(acc[mi][p * 2 + nn], ah[mi], bh[2 * nn], bh[2 * nn + 1]);
                                MMA(acc[mi][p * 2 + nn], ah[mi], bl[2 * nn], bl[2 * nn + 1]);
                                MMA(acc[mi][p * 2 + nn], al[mi], bh[2 * nn], bh[2 * nn + 1]);
                            }
                    }
                }
            }
        }
    }

    // ---- epilogue: add bias, store float2 ----
    const int g = lane >> 2, tg = lane & 3;
#pragma unroll
    for (int mi = 0; mi < 2; ++mi) {
        int o1 = o0 + wm * 32 + mi * 16 + g;
        float bv1 = bias[o1], bv2 = bias[o1 + 8];
        float* r1 = out + ((size_t)(b * O_ + o1)) * T_ + t0 + wn * 64 + tg * 2;
        float* r2 = r1 + 8 * T_;
#pragma unroll
        for (int nf = 0; nf < 8; ++nf) {
            float2 v1 = make_float2(acc[mi][nf][0] + bv1, acc[mi][nf][1] + bv1);
            float2 v2 = make_float2(acc[mi][nf][2] + bv2, acc[mi][nf][3] + bv2);
            *(float2*)(r1 + nf * 8) = v1;
            *(float2*)(r2 + nf * 8) = v2;
        }
    }
}

// ---------------------------------------------------------------------------
// Launch (3 kernels)
// ---------------------------------------------------------------------------
extern "C" void kernel_launch(void* const* d_in, const int* in_sizes, int n_in,
                              void* d_out, int out_size) {
    const float* x      = (const float*)d_in[0];
    const float* weight = (const float*)d_in[1];
    const float* P      = (const float*)d_in[2];
    const float* bias   = (const float*)d_in[3];
    float* out          = (float*)d_out;

    xsplit<<<dim3(T_ / 32, C_ / 32, B_), 256>>>(x);
    build_k2<<<256, 256>>>(weight, P);

    cudaFuncSetAttribute(conv_mma, cudaFuncAttributeMaxDynamicSharedMemorySize, DSMEM);
    conv_mma<<<dim3(64, 2), 512, DSMEM>>>(bias, out);
}

// round 11
// speedup vs baseline: 1.1304x; 1.1024x over previous
#include <cuda_runtime.h>
#include <cuda_bf16.h>
#include <cstdint>

// ---------------------------------------------------------------------------
// Dcls1d via mma.sync (HMMA) bf16 split-GEMM with ACTIVE-d COMPACTION.
//   out[b,o,t] = bias[o] + sum_{d,i} K2[d,o,i] * x[b,i,t+d-16]
//   Most K2 d-slices are exactly zero; per-o nonzero masks (plain stores),
//   OR-reduced in conv prologue. fp32 = bf16 hi+lo, products hh+hl+lh.
// R11: A staging & sync are GROUP-LOCAL (4 warps sharing the same 32 o-rows,
//      named barrier) -> only 1 block barrier per ic-chunk. Fused prep kernel
//      with register-resident (gather-form) K2 build.
// ---------------------------------------------------------------------------

#define B_   8
#define C_   256
#define T_   2048
#define O_   256
#define DKS_ 33
#define KC_  16
#define TP_  2080   // 16 + 2048 + 16 padded time rows

__device__ __nv_bfloat16 g_Khi[DKS_ * O_ * C_];   // [d][o][i]
__device__ __nv_bfloat16 g_Klo[DKS_ * O_ * C_];
__device__ __nv_bfloat16 g_Xhi[B_ * TP_ * C_];    // [b][t+16][i]
__device__ __nv_bfloat16 g_Xlo[B_ * TP_ * C_];
__device__ unsigned long long g_maskblk[O_];      // per-o nonzero-slice mask

// ---- PTX helpers -----------------------------------------------------------
__device__ __forceinline__ uint32_t smem_u32(const void* p) {
    uint32_t a;
    asm("{ .reg .u64 t; cvta.to.shared.u64 t, %1; cvt.u32.u64 %0, t; }"
        : "=r"(a) : "l"(p));
    return a;
}
__device__ __forceinline__ void cpa16(uint32_t dst, const void* src) {
    asm volatile("cp.async.ca.shared.global [%0], [%1], 16;" :: "r"(dst), "l"(src));
}
#define CP_COMMIT() asm volatile("cp.async.commit_group;" ::: "memory")
#define CP_WAIT0()  asm volatile("cp.async.wait_group 0;" ::: "memory")
#define GROUP_BAR(id) asm volatile("bar.sync %0, 128;" :: "r"(id) : "memory")

__device__ __forceinline__ void ldmx4(uint32_t* r, uint32_t addr) {
    asm volatile("ldmatrix.sync.aligned.m8n8.x4.shared.b16 {%0,%1,%2,%3}, [%4];"
                 : "=r"(r[0]), "=r"(r[1]), "=r"(r[2]), "=r"(r[3]) : "r"(addr));
}
#define MMA(dv, a, b0v, b1v)                                                   \
    asm volatile("mma.sync.aligned.m16n8k16.row.col.f32.bf16.bf16.f32 "        \
                 "{%0,%1,%2,%3},{%4,%5,%6,%7},{%8,%9},{%0,%1,%2,%3};"          \
                 : "+f"((dv)[0]), "+f"((dv)[1]), "+f"((dv)[2]), "+f"((dv)[3])  \
                 : "r"((a)[0]), "r"((a)[1]), "r"((a)[2]), "r"((a)[3]),         \
                   "r"(b0v), "r"(b1v))

// ---------------------------------------------------------------------------
// Fused prep: blocks [0,4096) x transpose/split+pads; [4096,4352) build K2.
// ---------------------------------------------------------------------------
__global__ void prep(const float* __restrict__ x,
                     const float* __restrict__ w,
                     const float* __restrict__ P) {
    __shared__ float sm[32][33];
    __shared__ unsigned long long s_m[8];
    const int tid = threadIdx.x;

    if (blockIdx.x < 4096) {
        int blk = blockIdx.x;
        int t0 = (blk & 63) * 32;
        int i0 = ((blk >> 6) & 7) * 32;
        int b  = blk >> 9;
        int tl = tid & 31, th = tid >> 5;

        if ((blk & 63) == 0) {   // zero pads
#pragma unroll
            for (int k = 0; k < 2; ++k) {
                int e = tid + k * 256;
                int r = e >> 5, cc = e & 31;
                size_t o1 = ((size_t)b * TP_ + r) * C_ + i0 + cc;
                size_t o2 = ((size_t)b * TP_ + (TP_ - 16 + r)) * C_ + i0 + cc;
                g_Xhi[o1] = __float2bfloat16(0.f);
                g_Xlo[o1] = __float2bfloat16(0.f);
                g_Xhi[o2] = __float2bfloat16(0.f);
                g_Xlo[o2] = __float2bfloat16(0.f);
            }
        }
#pragma unroll
        for (int k = 0; k < 4; ++k) {
            int i = i0 + th + k * 8;
            sm[th + k * 8][tl] = x[((size_t)b * C_ + i) * T_ + t0 + tl];
        }
        __syncthreads();
#pragma unroll
        for (int k = 0; k < 4; ++k) {
            int t = t0 + th + k * 8;
            float v = sm[tl][th + k * 8];
            __nv_bfloat16 h = __float2bfloat16(v);
            __nv_bfloat16 l = __float2bfloat16(v - __bfloat162float(h));
            size_t idx = ((size_t)b * TP_ + t + 16) * C_ + i0 + tl;
            g_Xhi[idx] = h;
            g_Xlo[idx] = l;
        }
    } else {
        // ---- build_k2, gather form (no local memory) ----
        int bk = blockIdx.x - 4096;               // out-channel
        int oi = bk * 256 + tid;                  // tid = input channel
        const float* Prow  = P + (size_t)oi * KC_;
        const float* P0row = P + (size_t)tid * KC_;  // out-channel 0 (frac src)
        const float* Wrow  = w + (size_t)oi * KC_;

        int   pi[KC_];
        float c1[KC_], c2[KC_];
#pragma unroll
        for (int k = 0; k < KC_; ++k) {
            float pp  = Prow[k] + 16.f;
            pi[k]     = (int)floorf(pp);
            float pp0 = P0row[k] + 16.f;
            float fr  = pp0 - floorf(pp0);
            float wv  = Wrow[k];
            c1[k] = wv * (1.f - fr);
            c2[k] = wv * fr;
        }
        unsigned long long bits = 0ull;
#pragma unroll
        for (int d = 0; d < DKS_; ++d) {
            float v = 0.f;
#pragma unroll
            for (int k = 0; k < KC_; ++k) {
                if (pi[k] == d)     v += c1[k];
                if (pi[k] + 1 == d) v += c2[k];
            }
            if (v != 0.f) bits |= 1ull << d;
            __nv_bfloat16 h = __float2bfloat16(v);
            __nv_bfloat16 l = __float2bfloat16(v - __bfloat162float(h));
            size_t idx = (size_t)(d * O_ + bk) * C_ + tid;
            g_Khi[idx] = h;
            g_Klo[idx] = l;
        }
#pragma unroll
        for (int s = 16; s > 0; s >>= 1)
            bits |= __shfl_xor_sync(0xffffffffu, bits, s);
        if ((tid & 31) == 0) s_m[tid >> 5] = bits;
        __syncthreads();
        if (tid == 0) {
            unsigned long long m = 0ull;
#pragma unroll
            for (int q = 0; q < 8; ++q) m |= s_m[q];
            g_maskblk[bk] = m;
        }
    }
}

// ---------------------------------------------------------------------------
// GEMM kernel.
// Block: 128 o x 256 t, 512 threads (16 warps: 4Mx4N, warp = 32 o x 64 t).
// ic-chunk = 64 i (4 chunks). smem rows 144B (conflict-free LDSM).
//   A (K2[d] tile): 128 x 64 i, hi+lo, double buffered; each wm-group stages
//     and syncs ONLY its own 32 rows (named barrier wm+1).
//   X tile: 288 x 64 i, hi+lo (per-ic, block barrier).
// ---------------------------------------------------------------------------
#define ROWB   144u
#define A_TS   18432u      // one A tensor (128*144)
#define A_BUF  36864u      // hi+lo pair
#define X_OFF  73728u
#define X_TS   41472u      // one X tensor (288*144)
#define DSMEM  (73728u + 2u * 41472u + 128u)

// Group-local A staging: group wm stages its rows [wm*32, wm*32+32).
// gt = index of this thread within its 128-thread group.
__device__ __forceinline__ void stage_A_grp(uint32_t A0, int d, int slot,
                                            int o0, int ic, int wm, int gt) {
    uint32_t Ab = A0 + (uint32_t)slot * A_BUF;
#pragma unroll
    for (int k = 0; k < 4; ++k) {
        int idx = gt + k * 128;                  // 512 chunks (2 tensors x 32r x 8c)
        int tn  = idx >> 8;
        int r   = (idx >> 3) & 31;
        int c   = idx & 7;
        int row = wm * 32 + r;
        const __nv_bfloat16* src = (tn ? g_Klo : g_Khi)
            + ((size_t)(d * 256 + o0 + row) * 256 + ic * 64 + c * 8);
        cpa16(Ab + (uint32_t)tn * A_TS + row * ROWB + c * 16, src);
    }
}

__global__ __launch_bounds__(512, 1)
void conv_mma(const float* __restrict__ bias, float* __restrict__ out) {
    extern __shared__ char dsm_raw[];
    uint32_t raw  = smem_u32(dsm_raw);
    uint32_t base = (raw + 127u) & ~127u;

    __shared__ unsigned long long s_part[4];
    __shared__ int s_act[DKS_];
    __shared__ int s_n;

    const int tid  = threadIdx.x;
    const int lane = tid & 31, w = tid >> 5;
    const int wm = w & 3, wn = w >> 2;            // 4 M-warps x 4 N-warps
    const int gt = wn * 32 + lane;                // index within wm-group (0..127)
    const int b  = blockIdx.x >> 3;
    const int t0 = (blockIdx.x & 7) * 256;
    const int tile = blockIdx.y;
    const int o0 = tile * 128;

    // ---- prologue: OR-reduce 128 per-o masks -> active-d list ----
    if (tid < 128) {
        unsigned long long m = g_maskblk[o0 + tid];
#pragma unroll
        for (int s = 16; s > 0; s >>= 1)
            m |= __shfl_xor_sync(0xffffffffu, m, s);
        if (lane == 0) s_part[w] = m;
    }
    __syncthreads();
    if (tid == 0) {
        unsigned long long m = s_part[0] | s_part[1] | s_part[2] | s_part[3];
        int n = 0;
        for (int d = 0; d < DKS_; ++d)
            if (m & (1ull << d)) s_act[n++] = d;
        s_n = n;
    }
    __syncthreads();
    const int n_act = s_n;

    const uint32_t A0 = base;
    const uint32_t X0 = base + X_OFF;

    float acc[2][8][4];
#pragma unroll
    for (int mi = 0; mi < 2; ++mi)
#pragma unroll
        for (int nf = 0; nf < 8; ++nf)
#pragma unroll
            for (int q = 0; q < 4; ++q) acc[mi][nf][q] = 0.f;

    // ldmatrix per-lane row/col offsets
    const uint32_t a_r = (lane & 7) + 8 * ((lane >> 3) & 1);
    const uint32_t a_c = (uint32_t)(lane >> 4) * 16;
    const uint32_t b_r = (lane & 7) + 8 * (lane >> 4);
    const uint32_t b_c = (uint32_t)((lane >> 3) & 1) * 16;

    for (int ic = 0; ic < 4 && n_act > 0; ++ic) {
        __syncthreads();    // all groups done with X (and A bufs) of prev ic
        // ---- stage X tile (288 rows x 64 i, hi+lo): 4608 chunks ----
#pragma unroll
        for (int k = 0; k < 9; ++k) {
            int idx = tid + k * 512;
            int tn  = idx >= 2304;
            int r   = (idx - tn * 2304) >> 3;
            int c   = idx & 7;
            const __nv_bfloat16* src = (tn ? g_Xlo : g_Xhi)
                + ((size_t)(b * TP_ + t0 + r) * 256 + ic * 64 + c * 8);
            cpa16(X0 + (uint32_t)tn * X_TS + r * ROWB + c * 16, src);
        }
        // ---- stage A(act[0]) group rows into buf0 ----
        stage_A_grp(A0, s_act[0], 0, o0, ic, wm, gt);
        CP_COMMIT();

#pragma unroll 1
        for (int j = 0; j < n_act; ++j) {
            const int d = s_act[j];
            CP_WAIT0();            // own X+A(j) chunks landed
            if (j == 0) __syncthreads();   // X visible to all
            else        GROUP_BAR(wm + 1); // A(j) visible within group;
                                           // group done reading slot (j+1)&1

            if (j < n_act - 1) {   // overlap A(j+1) group-copy with compute(j)
                stage_A_grp(A0, s_act[j + 1], (j + 1) & 1, o0, ic, wm, gt);
                CP_COMMIT();
            }

            const uint32_t Ab = A0 + (uint32_t)(j & 1) * A_BUF;
#pragma unroll
            for (int kk = 0; kk < 4; ++kk) {
                uint32_t ah[2][4], al[2][4];
#pragma unroll
                for (int mi = 0; mi < 2; ++mi) {
                    uint32_t ad = Ab + (wm * 32 + mi * 16 + a_r) * ROWB
                                + kk * 32 + a_c;
                    ldmx4(ah[mi], ad);
                    ldmx4(al[mi], ad + A_TS);
                }
#pragma unroll
                for (int p = 0; p < 4; ++p) {
                    uint32_t bh[4], bl[4];
                    uint32_t bd = X0 + (wn * 64 + d + p * 16 + b_r) * ROWB
                                + kk * 32 + b_c;
                    ldmx4(bh, bd);
                    ldmx4(bl, bd + X_TS);
#pragma unroll
                    for (int mi = 0; mi < 2; ++mi)
#pragma unroll
                        for (int nn = 0; nn < 2; ++nn) {
                            MMA(acc[mi][p * 2 + nn], ah[mi], bh[2 * nn], bh[2 * nn + 1]);
                            MMA(acc[mi][p * 2 + nn], ah[mi], bl[2 * nn], bl[2 * nn + 1]);
                            MMA(acc[mi][p * 2 + nn], al[mi], bh[2 * nn], bh[2 * nn + 1]);
                        }
                }
            }
        }
    }

    // ---- epilogue: add bias, store float2 ----
    const int g = lane >> 2, tg = lane & 3;
#pragma unroll
    for (int mi = 0; mi < 2; ++mi) {
        int o1 = o0 + wm * 32 + mi * 16 + g;
        float bv1 = bias[o1], bv2 = bias[o1 + 8];
        float* r1 = out + ((size_t)(b * O_ + o1)) * T_ + t0 + wn * 64 + tg * 2;
        float* r2 = r1 + 8 * T_;
#pragma unroll
        for (int nf = 0; nf < 8; ++nf) {
            float2 v1 = make_float2(acc[mi][nf][0] + bv1, acc[mi][nf][1] + bv1);
            float2 v2 = make_float2(acc[mi][nf][2] + bv2, acc[mi][nf][3] + bv2);
            *(float2*)(r1 + nf * 8) = v1;
            *(float2*)(r2 + nf * 8) = v2;
        }
    }
}

// ---------------------------------------------------------------------------
// Launch (2 kernels)
// ---------------------------------------------------------------------------
extern "C" void kernel_launch(void* const* d_in, const int* in_sizes, int n_in,
                              void* d_out, int out_size) {
    const float* x      = (const float*)d_in[0];
    const float* weight = (const float*)d_in[1];
    const float* P      = (const float*)d_in[2];
    const float* bias   = (const float*)d_in[3];
    float* out          = (float*)d_out;

    prep<<<4096 + 256, 256>>>(x, weight, P);

    cudaFuncSetAttribute(conv_mma, cudaFuncAttributeMaxDynamicSharedMemorySize, DSMEM);
    conv_mma<<<dim3(64, 2), 512, DSMEM>>>(bias, out);
}